// round 14
// baseline (speedup 1.0000x reference)
#include <cuda_runtime.h>
#include <math.h>
#include <stdint.h>

#define NROWS 32768
#define DDIM  512
#define KCB   8192
#define EPSF  1e-12f

#define BM 128
#define BN 128
#define BK 128                      // int8 elements (=bytes) per step
#define KSTA_B 528                  // A smem row stride bytes -> conflict-free LDSM
#define KSTB_B 144                  // B smem row stride bytes -> conflict-free LDSM
#define GEMM_THREADS 512
#define A_BYTES    (BM * KSTA_B)              // 67584
#define BSTG_BYTES (BN * KSTB_B)              // 18432
#define SMEM_BYTES (A_BYTES + 2 * BSTG_BYTES) // 104448
#define NSTEP ((KCB / BN) * (DDIM / BK))      // 64 * 4 = 256

#define WSCALE 1411.0f              // 127/0.09; wn entries hard-bounded ~0.083

// ---------------- device scratch ----------------
__device__ __align__(128) uint8_t g_x8[(size_t)NROWS*DDIM];
__device__ __align__(128) uint8_t g_w8[(size_t)KCB*DDIM];
__device__ __align__(128) float g_xn[(size_t)NROWS*DDIM];
__device__ __align__(128) float g_wn[(size_t)KCB*DDIM];
__device__ float g_xsq[NROWS];
__device__ float g_wsq[KCB];
__device__ int   g_top16[NROWS*16];
__device__ float g_rowsum[NROWS];

// ---------------- compensated arithmetic ----------------
__device__ __forceinline__ void twosum(float a, float b, float& s, float& e) {
    s = a + b;
    float bp = s - a;
    e = (a - (s - bp)) + (b - bp);
}
__device__ __forceinline__ void acc_prod(float x, float w, float& s, float& c) {
    float p = x * w;
    float pe = fmaf(x, w, -p);
    float t, e;
    twosum(s, p, t, e);
    s = t;
    c += e + pe;
}

// ---------------- prep: normalize -> fp32 xn, int8 quant, exact xsq ----------------
// gscale > 0: global scale (w). gscale <= 0: per-row max-abs scale (x; rank-invariant).
__global__ void prep_kernel(const float* __restrict__ v, int rows,
                            float* __restrict__ vn,
                            uint8_t* __restrict__ q8,
                            float* __restrict__ sq,
                            float gscale) {
    int warp = (blockIdx.x * blockDim.x + threadIdx.x) >> 5;
    int lane = threadIdx.x & 31;
    if (warp >= rows) return;
    const float* row = v + (size_t)warp * DDIM;
    float vals[16];
    float s = 0.f;
#pragma unroll
    for (int i = 0; i < 16; i++) { vals[i] = row[lane + 32*i]; s = fmaf(vals[i], vals[i], s); }
#pragma unroll
    for (int o = 16; o; o >>= 1) s += __shfl_xor_sync(0xffffffffu, s, o);
    float nrm = fmaxf(sqrtf(s), EPSF);

    float xnv[16];
    float s2 = 0.f, c2 = 0.f, mx = 0.f;
#pragma unroll
    for (int i = 0; i < 16; i++) {
        float xn = vals[i] / nrm;
        xnv[i] = xn;
        vn[(size_t)warp * DDIM + lane + 32*i] = xn;
        mx = fmaxf(mx, fabsf(xn));
        acc_prod(xn, xn, s2, c2);
    }
#pragma unroll
    for (int o = 16; o; o >>= 1) {
        float os = __shfl_xor_sync(0xffffffffu, s2, o);
        float oc = __shfl_xor_sync(0xffffffffu, c2, o);
        float t, e;
        twosum(s2, os, t, e);
        s2 = t; c2 += oc + e;
        mx = fmaxf(mx, __shfl_xor_sync(0xffffffffu, mx, o));
    }
    if (lane == 0) sq[warp] = s2 + c2;

    float scale = (gscale > 0.f) ? gscale : (127.0f / fmaxf(mx, 1e-20f));
#pragma unroll
    for (int i = 0; i < 16; i++) {
        int q = __float2int_rn(xnv[i] * scale);
        q = max(-127, min(127, q));
        q8[(size_t)warp * DDIM + lane + 32*i] = (uint8_t)(int8_t)q;
    }
}

// ---------------- top-S insert (tie: lower index wins) ----------------
template<int S>
__device__ __forceinline__ void topk_insert(float (&d)[S], int (&ix)[S], float nd, int ni) {
#pragma unroll
    for (int s = S - 1; s >= 0; s--) {
        bool better = (nd < d[s]) || (nd == d[s] && ni < ix[s]);
        if (!better) {
#pragma unroll
            for (int t = S - 1; t > s + 1; t--) { d[t] = d[t-1]; ix[t] = ix[t-1]; }
            if (s + 1 < S) { d[s+1] = nd; ix[s+1] = ni; }
            return;
        }
    }
#pragma unroll
    for (int t = S - 1; t > 0; t--) { d[t] = d[t-1]; ix[t] = ix[t-1]; }
    d[0] = nd; ix[0] = ni;
}

// ---------------- helpers ----------------
__device__ __forceinline__ uint32_t smem_u32(const void* p) {
    uint32_t a;
    asm("{ .reg .u64 t; cvta.to.shared.u64 t, %1; cvt.u32.u64 %0, t; }" : "=r"(a) : "l"(p));
    return a;
}
__device__ __forceinline__ void cp16(uint32_t sa, const void* g) {
    asm volatile("cp.async.cg.shared.global [%0], [%1], 16;" :: "r"(sa), "l"(g));
}
__device__ __forceinline__ void ldsm_x4(uint32_t (&r)[4], uint32_t addr) {
    asm volatile("ldmatrix.sync.aligned.m8n8.x4.shared.b16 {%0,%1,%2,%3}, [%4];"
                 : "=r"(r[0]), "=r"(r[1]), "=r"(r[2]), "=r"(r[3]) : "r"(addr));
}

#define MMA_S8(C, A0, A1, A2, A3, B0, B1) \
    asm volatile("mma.sync.aligned.m16n8k32.row.col.s32.s8.s8.s32 " \
                 "{%0,%1,%2,%3},{%4,%5,%6,%7},{%8,%9},{%0,%1,%2,%3};" \
                 : "+r"(C[0]), "+r"(C[1]), "+r"(C[2]), "+r"(C[3]) \
                 : "r"(A0), "r"(A1), "r"(A2), "r"(A3), "r"(B0), "r"(B1))

// ---------------- A-resident int8 GEMM + top-16 nomination (rank by -dot_int) ----------------
__global__ __launch_bounds__(GEMM_THREADS, 1)
void gemm_topk_kernel() {
    extern __shared__ __align__(16) char dynsm[];

    const uint32_t sm0 = smem_u32(dynsm);
    const int tid  = threadIdx.x;
    const int warp = tid >> 5, lane = tid & 31;
    const int wm = warp >> 2, wn = warp & 3;   // 4x4 warp grid, warp tile 32x32
    const int gI = lane >> 2, tig = lane & 3;
    const int mat = lane >> 3, rowin = lane & 7;
    const int row0 = blockIdx.x * BM;

    // ---- A tile resident: 128 x 512 int8, row stride 528B ----
#pragma unroll
    for (int i = 0; i < 8; i++) {
        int u = i * 512 + tid;            // 16B chunk id, 0..4095 (32 per row)
        int r = u >> 5, q = u & 31;
        cp16(sm0 + (uint32_t)(r * KSTA_B + q * 16),
             &g_x8[(size_t)(row0 + r) * DDIM + q * 16]);
    }
    asm volatile("cp.async.commit_group;");

    // ---- B chunk 0 prefetch ----
    {
#pragma unroll
        for (int i = 0; i < 2; i++) {
            int u = i * 512 + tid;        // 0..1023
            int r = u >> 3, q = u & 7;
            cp16(sm0 + (uint32_t)(A_BYTES + r * KSTB_B + q * 16),
                 &g_w8[(size_t)r * DDIM + q * 16]);
        }
        asm volatile("cp.async.commit_group;");
    }

    // ldmatrix base offsets (verified 8-bit k32 layout)
    uint32_t offA[2], offB[2];
#pragma unroll
    for (int mt = 0; mt < 2; mt++)
        offA[mt] = (uint32_t)((wm*32 + mt*16 + (mat&1)*8 + rowin) * KSTA_B
                              + (mat>>1)*16);
#pragma unroll
    for (int np = 0; np < 2; np++)
        offB[np] = (uint32_t)(A_BYTES + (wn*32 + np*16 + (mat>>1)*8 + rowin) * KSTB_B
                              + (mat&1)*16);

    float td[4][4]; int ti[4][4];
#pragma unroll
    for (int s = 0; s < 4; s++)
#pragma unroll
        for (int j = 0; j < 4; j++) { td[s][j] = INFINITY; ti[s][j] = 0x7fffffff; }

    int acc[2][4][4];
#pragma unroll
    for (int mt = 0; mt < 2; mt++)
#pragma unroll
        for (int nt = 0; nt < 4; nt++)
#pragma unroll
            for (int j = 0; j < 4; j++) acc[mt][nt][j] = 0;

    for (int c = 0; c < NSTEP; c++) {
        const int kt = c >> 2, dt = c & 3;

        asm volatile("cp.async.wait_group 0;");
        __syncthreads();

        if (c + 1 < NSTEP) {
            const int cn = c + 1;
            const int ktn = (cn >> 2) * BN, kofn = (cn & 3) * BK;
            const uint32_t stg = (uint32_t)(A_BYTES + (cn & 1) * BSTG_BYTES);
#pragma unroll
            for (int i = 0; i < 2; i++) {
                int u = i * 512 + tid;
                int r = u >> 3, q = u & 7;
                cp16(sm0 + stg + (uint32_t)(r * KSTB_B + q * 16),
                     &g_w8[(size_t)(ktn + r) * DDIM + kofn + q * 16]);
            }
            asm volatile("cp.async.commit_group;");
        }

        const uint32_t dtoffA = (uint32_t)(dt * BK);
        const uint32_t bstg   = (uint32_t)((c & 1) * BSTG_BYTES);

#pragma unroll
        for (int kc = 0; kc < 4; kc++) {
            const uint32_t ka = dtoffA + (uint32_t)(kc * 32);
            const uint32_t kb = bstg   + (uint32_t)(kc * 32);
            uint32_t a[2][4], b[2][4];
            ldsm_x4(a[0], sm0 + offA[0] + ka);
            ldsm_x4(a[1], sm0 + offA[1] + ka);
            ldsm_x4(b[0], sm0 + offB[0] + kb);
            ldsm_x4(b[1], sm0 + offB[1] + kb);

            MMA_S8(acc[0][0], a[0][0],a[0][1],a[0][2],a[0][3], b[0][0],b[0][1]);
            MMA_S8(acc[0][1], a[0][0],a[0][1],a[0][2],a[0][3], b[0][2],b[0][3]);
            MMA_S8(acc[0][2], a[0][0],a[0][1],a[0][2],a[0][3], b[1][0],b[1][1]);
            MMA_S8(acc[0][3], a[0][0],a[0][1],a[0][2],a[0][3], b[1][2],b[1][3]);
            MMA_S8(acc[1][0], a[1][0],a[1][1],a[1][2],a[1][3], b[0][0],b[0][1]);
            MMA_S8(acc[1][1], a[1][0],a[1][1],a[1][2],a[1][3], b[0][2],b[0][3]);
            MMA_S8(acc[1][2], a[1][0],a[1][1],a[1][2],a[1][3], b[1][0],b[1][1]);
            MMA_S8(acc[1][3], a[1][0],a[1][1],a[1][2],a[1][3], b[1][2],b[1][3]);
        }

        if (dt == 3) {
#pragma unroll
            for (int mt = 0; mt < 2; mt++)
#pragma unroll
                for (int nt = 0; nt < 4; nt++) {
                    int colb = wn*32 + nt*8 + tig*2;
                    int gc = kt * BN + colb;
                    topk_insert<4>(td[mt*2],   ti[mt*2],   -(float)acc[mt][nt][0], gc);
                    topk_insert<4>(td[mt*2],   ti[mt*2],   -(float)acc[mt][nt][1], gc+1);
                    topk_insert<4>(td[mt*2+1], ti[mt*2+1], -(float)acc[mt][nt][2], gc);
                    topk_insert<4>(td[mt*2+1], ti[mt*2+1], -(float)acc[mt][nt][3], gc+1);
                    acc[mt][nt][0] = 0; acc[mt][nt][1] = 0;
                    acc[mt][nt][2] = 0; acc[mt][nt][3] = 0;
                }
        }
    }
    __syncthreads();

    // cross-thread reduce: 16 owners/row x top-4 = 64 candidates -> top-16 (scratch over A)
    float* cd = (float*)dynsm;                          // [BM][64]
    int*   ci = (int*)(dynsm + BM*64*sizeof(float));    // [BM][64]
#pragma unroll
    for (int s = 0; s < 4; s++) {
        int rl = wm*32 + (s>>1)*16 + (s&1)*8 + gI;
        int cs = (wn*4 + tig)*4;
#pragma unroll
        for (int j = 0; j < 4; j++) {
            cd[rl*64 + cs + j] = td[s][j];
            ci[rl*64 + cs + j] = ti[s][j];
        }
    }
    __syncthreads();

    if (tid < BM) {
        float bd[16]; int bi[16];
#pragma unroll
        for (int s = 0; s < 16; s++) { bd[s] = INFINITY; bi[s] = 0x7fffffff; }
        for (int cc = 0; cc < 64; cc++)
            topk_insert<16>(bd, bi, cd[tid*64 + cc], ci[tid*64 + cc]);
        int r = row0 + tid;
#pragma unroll
        for (int s = 0; s < 16; s++) g_top16[r*16 + s] = bi[s];
    }
}

// ---------------- epilogue: exact refine (warp/candidate x16), weights, quantize, loss ----------------
__global__ __launch_bounds__(512)
void epilogue_kernel(const float* __restrict__ x, const float* __restrict__ emb,
                     float* __restrict__ out) {
    const int n = blockIdx.x;
    const int t = threadIdx.x;     // 512 threads, 16 warps
    const int w = t >> 5, lane = t & 31;
    __shared__ int   cidx[16];
    __shared__ float dist16[16];
    __shared__ float ws[3];
    __shared__ int   sel[3];
    __shared__ float red[512];

    if (t < 16) cidx[t] = g_top16[n*16 + t];
    __syncthreads();

    // warp w: compensated-exact dot(xn, wn[cidx[w]])
    {
        const float* xr = g_xn + (size_t)n * DDIM;
        const float* wr = g_wn + (size_t)cidx[w] * DDIM;
        float s = 0.f, c = 0.f;
#pragma unroll
        for (int i = 0; i < 16; i++)
            acc_prod(xr[lane + 32*i], wr[lane + 32*i], s, c);
#pragma unroll
        for (int o = 16; o; o >>= 1) {
            float os = __shfl_xor_sync(0xffffffffu, s, o);
            float oc = __shfl_xor_sync(0xffffffffu, c, o);
            float tt, e;
            twosum(s, os, tt, e);
            s = tt; c += oc + e;
        }
        if (lane == 0)
            dist16[w] = g_xsq[n] + g_wsq[cidx[w]] - 2.f * (s + c);
    }
    __syncthreads();

    if (t == 0) {
        float bd[3] = {INFINITY, INFINITY, INFINITY};
        int   bs[3] = {0, 0, 0};
        bool  hv[3] = {false, false, false};
        for (int c = 0; c < 16; c++) {
            float nd = dist16[c]; int ni = cidx[c];
            if (!hv[2] || nd < bd[2] || (nd == bd[2] && ni < cidx[bs[2]])) {
                if (!hv[1] || nd < bd[1] || (nd == bd[1] && ni < cidx[bs[1]])) {
                    bd[2] = bd[1]; bs[2] = bs[1]; hv[2] = hv[1];
                    if (!hv[0] || nd < bd[0] || (nd == bd[0] && ni < cidx[bs[0]])) {
                        bd[1] = bd[0]; bs[1] = bs[0]; hv[1] = hv[0];
                        bd[0] = nd;   bs[0] = c;     hv[0] = true;
                    } else { bd[1] = nd; bs[1] = c; hv[1] = true; }
                } else { bd[2] = nd; bs[2] = c; hv[2] = true; }
            }
        }
        float v0 = 1.f/bd[0], v1 = 1.f/bd[1], v2 = 1.f/bd[2];
        float ssum = (v0 + v1) + v2;
        ws[0] = v0/ssum; ws[1] = v1/ssum; ws[2] = v2/ssum;
        sel[0] = cidx[bs[0]]; sel[1] = cidx[bs[1]]; sel[2] = cidx[bs[2]];
        float* idx_out = out + (size_t)NROWS*DDIM + 1;
        idx_out[n*3+0] = (float)sel[0];
        idx_out[n*3+1] = (float)sel[1];
        idx_out[n*3+2] = (float)sel[2];
    }
    __syncthreads();

    const float w0 = ws[0], w1 = ws[1], w2 = ws[2];
    const float* e0 = emb + (size_t)sel[0]*DDIM;
    const float* e1 = emb + (size_t)sel[1]*DDIM;
    const float* e2 = emb + (size_t)sel[2]*DDIM;

    float local = 0.f;
    {
        int d = t;   // DDIM == 512 == blockDim
        float q  = fmaf(w2, e2[d], fmaf(w1, e1[d], w0*e0[d]));
        float xv = x[(size_t)n*DDIM + d];
        float diff = q - xv;
        out[(size_t)n*DDIM + d] = xv + diff;
        local = diff * diff;
    }
    red[t] = local;
    __syncthreads();
#pragma unroll
    for (int o = 256; o; o >>= 1) {
        if (t < o) red[t] += red[t+o];
        __syncthreads();
    }
    if (t == 0) g_rowsum[n] = red[0];
}

// ---------------- deterministic loss reduction ----------------
__global__ void loss_kernel(float* __restrict__ out) {
    __shared__ double red[256];
    int t = threadIdx.x;
    double s = 0.0;
    for (int i = t; i < NROWS; i += 256) s += (double)g_rowsum[i];
    red[t] = s;
    __syncthreads();
#pragma unroll
    for (int o = 128; o; o >>= 1) {
        if (t < o) red[t] += red[t+o];
        __syncthreads();
    }
    if (t == 0) {
        double mean = red[0] / (double)((size_t)NROWS*DDIM);
        out[(size_t)NROWS*DDIM] = (float)(1.25 * mean);
    }
}

// ---------------- launch ----------------
extern "C" void kernel_launch(void* const* d_in, const int* in_sizes, int n_in,
                              void* d_out, int out_size) {
    const float* x   = (const float*)d_in[0];
    const float* emb = (const float*)d_in[1];
    float* out = (float*)d_out;

    uint8_t *p_x8, *p_w8;
    float *p_xn, *p_wn, *p_xsq, *p_wsq;
    cudaGetSymbolAddress((void**)&p_x8,  g_x8);
    cudaGetSymbolAddress((void**)&p_w8,  g_w8);
    cudaGetSymbolAddress((void**)&p_xn,  g_xn);
    cudaGetSymbolAddress((void**)&p_wn,  g_wn);
    cudaGetSymbolAddress((void**)&p_xsq, g_xsq);
    cudaGetSymbolAddress((void**)&p_wsq, g_wsq);

    cudaFuncSetAttribute(gemm_topk_kernel,
                         cudaFuncAttributeMaxDynamicSharedMemorySize, SMEM_BYTES);

    prep_kernel<<<KCB/8,   256>>>(emb, KCB,   p_wn, p_w8, p_wsq, WSCALE);
    prep_kernel<<<NROWS/8, 256>>>(x,   NROWS, p_xn, p_x8, p_xsq, -1.0f);
    gemm_topk_kernel<<<NROWS/BM, GEMM_THREADS, SMEM_BYTES>>>();
    epilogue_kernel<<<NROWS, 512>>>(x, emb, out);
    loss_kernel<<<1, 256>>>(out);
}

// round 15
// speedup vs baseline: 1.1042x; 1.1042x over previous
#include <cuda_runtime.h>
#include <cuda_bf16.h>
#include <math.h>
#include <stdint.h>

#define NROWS 32768
#define DDIM  512
#define KCB   8192
#define EPSF  1e-12f

#define BM 128
#define BN 128
#define BK 128                      // bf16 elements per step
#define KSTA 520                    // A smem row stride (bf16): 1040B -> conflict-free LDSM
#define KSTB 136                    // B smem row stride (bf16): 272B  -> conflict-free LDSM
#define GEMM_THREADS 512
#define A_BYTES    (BM * KSTA * 2)            // 133120
#define BSTG_BYTES (BN * KSTB * 2)            // 34816
#define SMEM_BYTES (A_BYTES + 2 * BSTG_BYTES) // 202752
#define NSTEP ((KCB / BN) * (DDIM / BK))      // 64 * 4 = 256

// ---------------- device scratch ----------------
__device__ __align__(128) __nv_bfloat16 g_xh[(size_t)NROWS*DDIM];
__device__ __align__(128) __nv_bfloat16 g_wh[(size_t)KCB*DDIM];
__device__ __align__(128) float g_xn[(size_t)NROWS*DDIM];
__device__ __align__(128) float g_wn[(size_t)KCB*DDIM];
__device__ float g_xsq[NROWS];
__device__ float g_wsq[KCB];
__device__ int   g_top8[NROWS*8];
__device__ float g_rowsum[NROWS];

// ---------------- compensated arithmetic ----------------
__device__ __forceinline__ void twosum(float a, float b, float& s, float& e) {
    s = a + b;
    float bp = s - a;
    e = (a - (s - bp)) + (b - bp);
}
__device__ __forceinline__ void acc_prod(float x, float w, float& s, float& c) {
    float p = x * w;
    float pe = fmaf(x, w, -p);
    float t, e;
    twosum(s, p, t, e);
    s = t;
    c += e + pe;
}

// ---------------- prep: normalize -> fp32 xn, bf16, exact xsq ----------------
__global__ void prep_kernel(const float* __restrict__ v, int rows,
                            float* __restrict__ vn,
                            __nv_bfloat16* __restrict__ hi,
                            float* __restrict__ sq) {
    int warp = (blockIdx.x * blockDim.x + threadIdx.x) >> 5;
    int lane = threadIdx.x & 31;
    if (warp >= rows) return;
    const float* row = v + (size_t)warp * DDIM;
    float vals[16];
    float s = 0.f;
#pragma unroll
    for (int i = 0; i < 16; i++) { vals[i] = row[lane + 32*i]; s = fmaf(vals[i], vals[i], s); }
#pragma unroll
    for (int o = 16; o; o >>= 1) s += __shfl_xor_sync(0xffffffffu, s, o);
    float nrm = fmaxf(sqrtf(s), EPSF);
    float s2 = 0.f, c2 = 0.f;
#pragma unroll
    for (int i = 0; i < 16; i++) {
        float xn = vals[i] / nrm;
        size_t off = (size_t)warp * DDIM + lane + 32*i;
        vn[off] = xn;
        hi[off] = __float2bfloat16(xn);
        acc_prod(xn, xn, s2, c2);
    }
#pragma unroll
    for (int o = 16; o; o >>= 1) {
        float os = __shfl_xor_sync(0xffffffffu, s2, o);
        float oc = __shfl_xor_sync(0xffffffffu, c2, o);
        float t, e;
        twosum(s2, os, t, e);
        s2 = t; c2 += oc + e;
    }
    if (lane == 0) sq[warp] = s2 + c2;
}

// ---------------- top-S insert (tie: lower index wins) ----------------
template<int S>
__device__ __forceinline__ void topk_insert(float (&d)[S], int (&ix)[S], float nd, int ni) {
#pragma unroll
    for (int s = S - 1; s >= 0; s--) {
        bool better = (nd < d[s]) || (nd == d[s] && ni < ix[s]);
        if (!better) {
#pragma unroll
            for (int t = S - 1; t > s + 1; t--) { d[t] = d[t-1]; ix[t] = ix[t-1]; }
            if (s + 1 < S) { d[s+1] = nd; ix[s+1] = ni; }
            return;
        }
    }
#pragma unroll
    for (int t = S - 1; t > 0; t--) { d[t] = d[t-1]; ix[t] = ix[t-1]; }
    d[0] = nd; ix[0] = ni;
}

// ---------------- helpers ----------------
__device__ __forceinline__ uint32_t smem_u32(const void* p) {
    uint32_t a;
    asm("{ .reg .u64 t; cvta.to.shared.u64 t, %1; cvt.u32.u64 %0, t; }" : "=r"(a) : "l"(p));
    return a;
}
__device__ __forceinline__ void cp16(uint32_t sa, const void* g) {
    asm volatile("cp.async.cg.shared.global [%0], [%1], 16;" :: "r"(sa), "l"(g));
}
__device__ __forceinline__ void ldsm_x4(uint32_t (&r)[4], uint32_t addr) {
    asm volatile("ldmatrix.sync.aligned.m8n8.x4.shared.b16 {%0,%1,%2,%3}, [%4];"
                 : "=r"(r[0]), "=r"(r[1]), "=r"(r[2]), "=r"(r[3]) : "r"(addr));
}

#define MMA_BF16(C, A0, A1, A2, A3, B0, B1) \
    asm volatile("mma.sync.aligned.m16n8k16.row.col.f32.bf16.bf16.f32 " \
                 "{%0,%1,%2,%3},{%4,%5,%6,%7},{%8,%9},{%0,%1,%2,%3};" \
                 : "+f"(C[0]), "+f"(C[1]), "+f"(C[2]), "+f"(C[3]) \
                 : "r"(A0), "r"(A1), "r"(A2), "r"(A3), "r"(B0), "r"(B1))

// ---------------- A-resident bf16 GEMM + top-8 nomination ----------------
__global__ __launch_bounds__(GEMM_THREADS, 1)
void gemm_topk_kernel() {
    extern __shared__ __align__(16) char dynsm[];
    __shared__ float wsqs[BN];

    const uint32_t sm0 = smem_u32(dynsm);
    const int tid  = threadIdx.x;
    const int warp = tid >> 5, lane = tid & 31;
    const int wm = warp >> 2, wn = warp & 3;   // 4x4 warp grid, warp tile 32x32
    const int gI = lane >> 2, tig = lane & 3;
    const int mat = lane >> 3, rowin = lane & 7;
    const int row0 = blockIdx.x * BM;

    // ---- A tile resident: 128 x 512 bf16, stride KSTA ----
#pragma unroll
    for (int i = 0; i < 16; i++) {
        int u = i * 512 + tid;            // 16B chunk id, 0..8191 (64 per row)
        int r = u >> 6, q = u & 63;
        cp16(sm0 + (uint32_t)(r * (KSTA*2) + q * 16),
             &g_xh[(size_t)(row0 + r) * DDIM + q * 8]);
    }
    asm volatile("cp.async.commit_group;");

    // ---- B chunk 0 prefetch (kt=0, dt=0): 128 rows x 256B ----
    {
#pragma unroll
        for (int i = 0; i < 4; i++) {
            int u = i * 512 + tid;        // 0..2047
            int r = u >> 4, q = u & 15;
            cp16(sm0 + (uint32_t)(A_BYTES + r * (KSTB*2) + q * 16),
                 &g_wh[(size_t)r * DDIM + q * 8]);
        }
        asm volatile("cp.async.commit_group;");
    }

    // ldmatrix base offsets (k16 = 0)
    uint32_t offA[2], offB[2];
#pragma unroll
    for (int mt = 0; mt < 2; mt++)
        offA[mt] = (uint32_t)(((wm*32 + mt*16 + (mat&1)*8 + rowin) * KSTA
                               + (mat>>1)*8) * 2);
#pragma unroll
    for (int np = 0; np < 2; np++)
        offB[np] = (uint32_t)(A_BYTES + ((wn*32 + np*16 + (mat>>1)*8 + rowin) * KSTB
                               + (mat&1)*8) * 2);

    float xsq_r[4];
#pragma unroll
    for (int s = 0; s < 4; s++)
        xsq_r[s] = g_xsq[row0 + wm*32 + (s>>1)*16 + (s&1)*8 + gI];

    float td[4][3]; int ti[4][3];
#pragma unroll
    for (int s = 0; s < 4; s++) {
        td[s][0] = td[s][1] = td[s][2] = INFINITY;
        ti[s][0] = ti[s][1] = ti[s][2] = 0x7fffffff;
    }

    float acc[2][4][4];
#pragma unroll
    for (int mt = 0; mt < 2; mt++)
#pragma unroll
        for (int nt = 0; nt < 4; nt++)
#pragma unroll
            for (int j = 0; j < 4; j++) acc[mt][nt][j] = 0.f;

    for (int c = 0; c < NSTEP; c++) {
        const int kt = c >> 2, dt = c & 3;

        asm volatile("cp.async.wait_group 0;");
        __syncthreads();

        if (dt == 0 && tid < BN) wsqs[tid] = g_wsq[kt * BN + tid];

        if (c + 1 < NSTEP) {
            const int cn = c + 1;
            const int ktn = (cn >> 2) * BN, kofn = (cn & 3) * BK;
            const uint32_t stg = (uint32_t)(A_BYTES + (cn & 1) * BSTG_BYTES);
#pragma unroll
            for (int i = 0; i < 4; i++) {
                int u = i * 512 + tid;
                int r = u >> 4, q = u & 15;
                cp16(sm0 + stg + (uint32_t)(r * (KSTB*2) + q * 16),
                     &g_wh[(size_t)(ktn + r) * DDIM + kofn + q * 8]);
            }
            asm volatile("cp.async.commit_group;");
        }

        const uint32_t dtoffA = (uint32_t)(dt * BK * 2);           // bytes into A row
        const uint32_t bstg   = (uint32_t)((c & 1) * BSTG_BYTES);

#pragma unroll
        for (int k16 = 0; k16 < 8; k16++) {
            const uint32_t ka = dtoffA + (uint32_t)(k16 * 32);
            const uint32_t kb = bstg   + (uint32_t)(k16 * 32);
            uint32_t a[2][4], b[2][4];
            ldsm_x4(a[0], sm0 + offA[0] + ka);
            ldsm_x4(a[1], sm0 + offA[1] + ka);
            ldsm_x4(b[0], sm0 + offB[0] + kb);
            ldsm_x4(b[1], sm0 + offB[1] + kb);

            MMA_BF16(acc[0][0], a[0][0],a[0][1],a[0][2],a[0][3], b[0][0],b[0][1]);
            MMA_BF16(acc[0][1], a[0][0],a[0][1],a[0][2],a[0][3], b[0][2],b[0][3]);
            MMA_BF16(acc[0][2], a[0][0],a[0][1],a[0][2],a[0][3], b[1][0],b[1][1]);
            MMA_BF16(acc[0][3], a[0][0],a[0][1],a[0][2],a[0][3], b[1][2],b[1][3]);
            MMA_BF16(acc[1][0], a[1][0],a[1][1],a[1][2],a[1][3], b[0][0],b[0][1]);
            MMA_BF16(acc[1][1], a[1][0],a[1][1],a[1][2],a[1][3], b[0][2],b[0][3]);
            MMA_BF16(acc[1][2], a[1][0],a[1][1],a[1][2],a[1][3], b[1][0],b[1][1]);
            MMA_BF16(acc[1][3], a[1][0],a[1][1],a[1][2],a[1][3], b[1][2],b[1][3]);
        }

        if (dt == 3) {
#pragma unroll
            for (int mt = 0; mt < 2; mt++)
#pragma unroll
                for (int nt = 0; nt < 4; nt++) {
                    int colb = wn*32 + nt*8 + tig*2;
                    float w0 = wsqs[colb], w1 = wsqs[colb+1];
                    int gc = kt * BN + colb;
                    float d00 = xsq_r[mt*2]   + w0 - 2.f*acc[mt][nt][0];
                    float d01 = xsq_r[mt*2]   + w1 - 2.f*acc[mt][nt][1];
                    float d10 = xsq_r[mt*2+1] + w0 - 2.f*acc[mt][nt][2];
                    float d11 = xsq_r[mt*2+1] + w1 - 2.f*acc[mt][nt][3];
                    topk_insert<3>(td[mt*2],   ti[mt*2],   d00, gc);
                    topk_insert<3>(td[mt*2],   ti[mt*2],   d01, gc+1);
                    topk_insert<3>(td[mt*2+1], ti[mt*2+1], d10, gc);
                    topk_insert<3>(td[mt*2+1], ti[mt*2+1], d11, gc+1);
                    acc[mt][nt][0] = 0.f; acc[mt][nt][1] = 0.f;
                    acc[mt][nt][2] = 0.f; acc[mt][nt][3] = 0.f;
                }
        }
    }
    __syncthreads();

    // cross-thread reduce: 16 owners/row x top-3 = 48 candidates -> top-8 (scratch over A)
    float* cd = (float*)dynsm;                          // [BM][48]
    int*   ci = (int*)(dynsm + BM*48*sizeof(float));    // [BM][48]
#pragma unroll
    for (int s = 0; s < 4; s++) {
        int rl = wm*32 + (s>>1)*16 + (s&1)*8 + gI;
        int cs = (wn*4 + tig)*3;
#pragma unroll
        for (int j = 0; j < 3; j++) {
            cd[rl*48 + cs + j] = td[s][j];
            ci[rl*48 + cs + j] = ti[s][j];
        }
    }
    __syncthreads();

    if (tid < BM) {
        float bd[8]; int bi[8];
#pragma unroll
        for (int s = 0; s < 8; s++) { bd[s] = INFINITY; bi[s] = 0x7fffffff; }
        for (int cc = 0; cc < 48; cc++)
            topk_insert<8>(bd, bi, cd[tid*48 + cc], ci[tid*48 + cc]);
        int r = row0 + tid;
#pragma unroll
        for (int s = 0; s < 8; s++) g_top8[r*8 + s] = bi[s];
    }
}

// ---------------- epilogue: exact refine (warp per candidate), weights, quantize, loss ----------------
__global__ __launch_bounds__(256)
void epilogue_kernel(const float* __restrict__ x, const float* __restrict__ emb,
                     float* __restrict__ out) {
    const int n = blockIdx.x;
    const int t = threadIdx.x;
    const int w = t >> 5, lane = t & 31;
    __shared__ int   cidx[8];
    __shared__ float dist8[8];
    __shared__ float ws[3];
    __shared__ int   sel[3];
    __shared__ float red[256];

    if (t < 8) cidx[t] = g_top8[n*8 + t];
    __syncthreads();

    {
        const float* xr = g_xn + (size_t)n * DDIM;
        const float* wr = g_wn + (size_t)cidx[w] * DDIM;
        float s = 0.f, c = 0.f;
#pragma unroll
        for (int i = 0; i < 16; i++)
            acc_prod(xr[lane + 32*i], wr[lane + 32*i], s, c);
#pragma unroll
        for (int o = 16; o; o >>= 1) {
            float os = __shfl_xor_sync(0xffffffffu, s, o);
            float oc = __shfl_xor_sync(0xffffffffu, c, o);
            float tt, e;
            twosum(s, os, tt, e);
            s = tt; c += oc + e;
        }
        if (lane == 0)
            dist8[w] = g_xsq[n] + g_wsq[cidx[w]] - 2.f * (s + c);
    }
    __syncthreads();

    if (t == 0) {
        float bd[3] = {INFINITY, INFINITY, INFINITY};
        int   bs[3] = {0, 0, 0};
        bool  hv[3] = {false, false, false};
        for (int c = 0; c < 8; c++) {
            float nd = dist8[c]; int ni = cidx[c];
            if (!hv[2] || nd < bd[2] || (nd == bd[2] && ni < cidx[bs[2]])) {
                if (!hv[1] || nd < bd[1] || (nd == bd[1] && ni < cidx[bs[1]])) {
                    bd[2] = bd[1]; bs[2] = bs[1]; hv[2] = hv[1];
                    if (!hv[0] || nd < bd[0] || (nd == bd[0] && ni < cidx[bs[0]])) {
                        bd[1] = bd[0]; bs[1] = bs[0]; hv[1] = hv[0];
                        bd[0] = nd;   bs[0] = c;     hv[0] = true;
                    } else { bd[1] = nd; bs[1] = c; hv[1] = true; }
                } else { bd[2] = nd; bs[2] = c; hv[2] = true; }
            }
        }
        float v0 = 1.f/bd[0], v1 = 1.f/bd[1], v2 = 1.f/bd[2];
        float ssum = (v0 + v1) + v2;
        ws[0] = v0/ssum; ws[1] = v1/ssum; ws[2] = v2/ssum;
        sel[0] = cidx[bs[0]]; sel[1] = cidx[bs[1]]; sel[2] = cidx[bs[2]];
        float* idx_out = out + (size_t)NROWS*DDIM + 1;
        idx_out[n*3+0] = (float)sel[0];
        idx_out[n*3+1] = (float)sel[1];
        idx_out[n*3+2] = (float)sel[2];
    }
    __syncthreads();

    const float w0 = ws[0], w1 = ws[1], w2 = ws[2];
    const float* e0 = emb + (size_t)sel[0]*DDIM;
    const float* e1 = emb + (size_t)sel[1]*DDIM;
    const float* e2 = emb + (size_t)sel[2]*DDIM;

    float local = 0.f;
#pragma unroll
    for (int d = t; d < DDIM; d += 256) {
        float q  = fmaf(w2, e2[d], fmaf(w1, e1[d], w0*e0[d]));
        float xv = x[(size_t)n*DDIM + d];
        float diff = q - xv;
        out[(size_t)n*DDIM + d] = xv + diff;
        local = fmaf(diff, diff, local);
    }
    red[t] = local;
    __syncthreads();
#pragma unroll
    for (int o = 128; o; o >>= 1) {
        if (t < o) red[t] += red[t+o];
        __syncthreads();
    }
    if (t == 0) g_rowsum[n] = red[0];
}

// ---------------- deterministic loss reduction ----------------
__global__ void loss_kernel(float* __restrict__ out) {
    __shared__ double red[256];
    int t = threadIdx.x;
    double s = 0.0;
    for (int i = t; i < NROWS; i += 256) s += (double)g_rowsum[i];
    red[t] = s;
    __syncthreads();
#pragma unroll
    for (int o = 128; o; o >>= 1) {
        if (t < o) red[t] += red[t+o];
        __syncthreads();
    }
    if (t == 0) {
        double mean = red[0] / (double)((size_t)NROWS*DDIM);
        out[(size_t)NROWS*DDIM] = (float)(1.25 * mean);
    }
}

// ---------------- launch ----------------
extern "C" void kernel_launch(void* const* d_in, const int* in_sizes, int n_in,
                              void* d_out, int out_size) {
    const float* x   = (const float*)d_in[0];
    const float* emb = (const float*)d_in[1];
    float* out = (float*)d_out;

    __nv_bfloat16 *p_xh, *p_wh;
    float *p_xn, *p_wn, *p_xsq, *p_wsq;
    cudaGetSymbolAddress((void**)&p_xh,  g_xh);
    cudaGetSymbolAddress((void**)&p_wh,  g_wh);
    cudaGetSymbolAddress((void**)&p_xn,  g_xn);
    cudaGetSymbolAddress((void**)&p_wn,  g_wn);
    cudaGetSymbolAddress((void**)&p_xsq, g_xsq);
    cudaGetSymbolAddress((void**)&p_wsq, g_wsq);

    cudaFuncSetAttribute(gemm_topk_kernel,
                         cudaFuncAttributeMaxDynamicSharedMemorySize, SMEM_BYTES);

    prep_kernel<<<KCB/8,   256>>>(emb, KCB,   p_wn, p_wh, p_wsq);
    prep_kernel<<<NROWS/8, 256>>>(x,   NROWS, p_xn, p_xh, p_xsq);
    gemm_topk_kernel<<<NROWS/BM, GEMM_THREADS, SMEM_BYTES>>>();
    epilogue_kernel<<<NROWS, 256>>>(x, emb, out);
    loss_kernel<<<1, 256>>>(out);
}

// round 16
// speedup vs baseline: 1.8013x; 1.6313x over previous
#include <cuda_runtime.h>
#include <cuda_bf16.h>
#include <math.h>
#include <stdint.h>

#define NROWS 32768
#define DDIM  512
#define KCB   8192
#define EPSF  1e-12f

#define BM 128
#define BN 128
#define BK 64
#define KSTA 520                   // A smem row stride (bf16): 1040B -> conflict-free LDSM
#define KSTB 72                    // B smem row stride (bf16): 144B  -> conflict-free LDSM
#define GEMM_THREADS 512
#define A_BYTES    (BM * KSTA * 2)            // 133120
#define BSTG_BYTES (BN * KSTB * 2)            // 18432
#define SMEM_BYTES (A_BYTES + 2 * BSTG_BYTES) // 169984
#define NSTEP ((KCB / BN) * (DDIM / BK))      // 64 * 8 = 512

// ---------------- device scratch ----------------
__device__ __align__(128) __nv_bfloat16 g_xh[(size_t)NROWS*DDIM];
__device__ __align__(128) __nv_bfloat16 g_wh[(size_t)KCB*DDIM];
__device__ __align__(128) float g_xn[(size_t)NROWS*DDIM];
__device__ __align__(128) float g_wn[(size_t)KCB*DDIM];
__device__ float g_xsq[NROWS];
__device__ float g_wsq[KCB];
__device__ int   g_top8[NROWS*8];
__device__ float g_rowsum[NROWS];

// ---------------- compensated arithmetic ----------------
__device__ __forceinline__ void twosum(float a, float b, float& s, float& e) {
    s = a + b;
    float bp = s - a;
    e = (a - (s - bp)) + (b - bp);
}
__device__ __forceinline__ void acc_prod(float x, float w, float& s, float& c) {
    float p = x * w;
    float pe = fmaf(x, w, -p);
    float t, e;
    twosum(s, p, t, e);
    s = t;
    c += e + pe;
}

// ---------------- prep: normalize -> fp32 xn, bf16, exact xsq ----------------
__global__ void prep_kernel(const float* __restrict__ v, int rows,
                            float* __restrict__ vn,
                            __nv_bfloat16* __restrict__ hi,
                            float* __restrict__ sq) {
    int warp = (blockIdx.x * blockDim.x + threadIdx.x) >> 5;
    int lane = threadIdx.x & 31;
    if (warp >= rows) return;
    const float* row = v + (size_t)warp * DDIM;
    float vals[16];
    float s = 0.f;
#pragma unroll
    for (int i = 0; i < 16; i++) { vals[i] = row[lane + 32*i]; s = fmaf(vals[i], vals[i], s); }
#pragma unroll
    for (int o = 16; o; o >>= 1) s += __shfl_xor_sync(0xffffffffu, s, o);
    float nrm = fmaxf(sqrtf(s), EPSF);
    float s2 = 0.f, c2 = 0.f;
#pragma unroll
    for (int i = 0; i < 16; i++) {
        float xn = vals[i] / nrm;
        size_t off = (size_t)warp * DDIM + lane + 32*i;
        vn[off] = xn;
        hi[off] = __float2bfloat16(xn);
        acc_prod(xn, xn, s2, c2);
    }
#pragma unroll
    for (int o = 16; o; o >>= 1) {
        float os = __shfl_xor_sync(0xffffffffu, s2, o);
        float oc = __shfl_xor_sync(0xffffffffu, c2, o);
        float t, e;
        twosum(s2, os, t, e);
        s2 = t; c2 += oc + e;
    }
    if (lane == 0) sq[warp] = s2 + c2;
}

// ---------------- top-S insert (tie: lower index wins) ----------------
template<int S>
__device__ __forceinline__ void topk_insert(float (&d)[S], int (&ix)[S], float nd, int ni) {
#pragma unroll
    for (int s = S - 1; s >= 0; s--) {
        bool better = (nd < d[s]) || (nd == d[s] && ni < ix[s]);
        if (!better) {
#pragma unroll
            for (int t = S - 1; t > s + 1; t--) { d[t] = d[t-1]; ix[t] = ix[t-1]; }
            if (s + 1 < S) { d[s+1] = nd; ix[s+1] = ni; }
            return;
        }
    }
#pragma unroll
    for (int t = S - 1; t > 0; t--) { d[t] = d[t-1]; ix[t] = ix[t-1]; }
    d[0] = nd; ix[0] = ni;
}

// ---------------- helpers ----------------
__device__ __forceinline__ uint32_t smem_u32(const void* p) {
    uint32_t a;
    asm("{ .reg .u64 t; cvta.to.shared.u64 t, %1; cvt.u32.u64 %0, t; }" : "=r"(a) : "l"(p));
    return a;
}
__device__ __forceinline__ void cp16(uint32_t sa, const void* g) {
    asm volatile("cp.async.cg.shared.global [%0], [%1], 16;" :: "r"(sa), "l"(g));
}
__device__ __forceinline__ void ldsm_x4(uint32_t (&r)[4], uint32_t addr) {
    asm volatile("ldmatrix.sync.aligned.m8n8.x4.shared.b16 {%0,%1,%2,%3}, [%4];"
                 : "=r"(r[0]), "=r"(r[1]), "=r"(r[2]), "=r"(r[3]) : "r"(addr));
}

#define MMA_BF16(C, A0, A1, A2, A3, B0, B1) \
    asm volatile("mma.sync.aligned.m16n8k16.row.col.f32.bf16.bf16.f32 " \
                 "{%0,%1,%2,%3},{%4,%5,%6,%7},{%8,%9},{%0,%1,%2,%3};" \
                 : "+f"(C[0]), "+f"(C[1]), "+f"(C[2]), "+f"(C[3]) \
                 : "r"(A0), "r"(A1), "r"(A2), "r"(A3), "r"(B0), "r"(B1))

// ---------------- A-resident bf16 GEMM + top-8 nomination ----------------
__global__ __launch_bounds__(GEMM_THREADS, 1)
void gemm_topk_kernel() {
    extern __shared__ __align__(16) char dynsm[];
    __shared__ float wsqs[BN];

    const uint32_t sm0 = smem_u32(dynsm);
    const int tid  = threadIdx.x;
    const int warp = tid >> 5, lane = tid & 31;
    const int wm = warp >> 2, wn = warp & 3;   // 4x4 warp grid, warp tile 32x32
    const int gI = lane >> 2, tig = lane & 3;
    const int mat = lane >> 3, rowin = lane & 7;
    const int row0 = blockIdx.x * BM;

    // ---- A tile resident: 128 x 512 bf16, stride KSTA ----
#pragma unroll
    for (int i = 0; i < 16; i++) {
        int u = i * 512 + tid;            // 16B chunk id, 0..8191 (64 per row)
        int r = u >> 6, q = u & 63;
        cp16(sm0 + (uint32_t)(r * (KSTA*2) + q * 16),
             &g_xh[(size_t)(row0 + r) * DDIM + q * 8]);
    }
    asm volatile("cp.async.commit_group;");

    // ---- B chunk 0 prefetch (kt=0, dt=0) ----
    {
#pragma unroll
        for (int i = 0; i < 2; i++) {
            int u = i * 512 + tid;        // 0..1023
            int r = u >> 3, q = u & 7;
            cp16(sm0 + (uint32_t)(A_BYTES + r * (KSTB*2) + q * 16),
                 &g_wh[(size_t)r * DDIM + q * 8]);
        }
        asm volatile("cp.async.commit_group;");
    }

    // ldmatrix base offsets (k16 = 0)
    uint32_t offA[2], offB[2];
#pragma unroll
    for (int mt = 0; mt < 2; mt++)
        offA[mt] = (uint32_t)(((wm*32 + mt*16 + (mat&1)*8 + rowin) * KSTA
                               + (mat>>1)*8) * 2);
#pragma unroll
    for (int np = 0; np < 2; np++)
        offB[np] = (uint32_t)(A_BYTES + ((wn*32 + np*16 + (mat>>1)*8 + rowin) * KSTB
                               + (mat&1)*8) * 2);

    float xsq_r[4];
#pragma unroll
    for (int s = 0; s < 4; s++)
        xsq_r[s] = g_xsq[row0 + wm*32 + (s>>1)*16 + (s&1)*8 + gI];

    float td[4][3]; int ti[4][3];
#pragma unroll
    for (int s = 0; s < 4; s++) {
        td[s][0] = td[s][1] = td[s][2] = INFINITY;
        ti[s][0] = ti[s][1] = ti[s][2] = 0x7fffffff;
    }

    float acc[2][4][4];
#pragma unroll
    for (int mt = 0; mt < 2; mt++)
#pragma unroll
        for (int nt = 0; nt < 4; nt++)
#pragma unroll
            for (int j = 0; j < 4; j++) acc[mt][nt][j] = 0.f;

    for (int c = 0; c < NSTEP; c++) {
        const int kt = c >> 3, dt = c & 7;

        asm volatile("cp.async.wait_group 0;");
        __syncthreads();

        if (dt == 0 && tid < BN) wsqs[tid] = g_wsq[kt * BN + tid];

        if (c + 1 < NSTEP) {
            const int cn = c + 1;
            const int ktn = (cn >> 3) * BN, kofn = (cn & 7) * BK;
            const uint32_t stg = (uint32_t)(A_BYTES + (cn & 1) * BSTG_BYTES);
#pragma unroll
            for (int i = 0; i < 2; i++) {
                int u = i * 512 + tid;
                int r = u >> 3, q = u & 7;
                cp16(sm0 + stg + (uint32_t)(r * (KSTB*2) + q * 16),
                     &g_wh[(size_t)(ktn + r) * DDIM + kofn + q * 8]);
            }
            asm volatile("cp.async.commit_group;");
        }

        const uint32_t dtoffA = (uint32_t)(dt * BK * 2);           // bytes into A row
        const uint32_t bstg   = (uint32_t)((c & 1) * BSTG_BYTES);

#pragma unroll
        for (int k16 = 0; k16 < 4; k16++) {
            const uint32_t ka = dtoffA + (uint32_t)(k16 * 32);
            const uint32_t kb = bstg   + (uint32_t)(k16 * 32);
            uint32_t a[2][4], b[2][4];
            ldsm_x4(a[0], sm0 + offA[0] + ka);
            ldsm_x4(a[1], sm0 + offA[1] + ka);
            ldsm_x4(b[0], sm0 + offB[0] + kb);
            ldsm_x4(b[1], sm0 + offB[1] + kb);

            MMA_BF16(acc[0][0], a[0][0],a[0][1],a[0][2],a[0][3], b[0][0],b[0][1]);
            MMA_BF16(acc[0][1], a[0][0],a[0][1],a[0][2],a[0][3], b[0][2],b[0][3]);
            MMA_BF16(acc[0][2], a[0][0],a[0][1],a[0][2],a[0][3], b[1][0],b[1][1]);
            MMA_BF16(acc[0][3], a[0][0],a[0][1],a[0][2],a[0][3], b[1][2],b[1][3]);
            MMA_BF16(acc[1][0], a[1][0],a[1][1],a[1][2],a[1][3], b[0][0],b[0][1]);
            MMA_BF16(acc[1][1], a[1][0],a[1][1],a[1][2],a[1][3], b[0][2],b[0][3]);
            MMA_BF16(acc[1][2], a[1][0],a[1][1],a[1][2],a[1][3], b[1][0],b[1][1]);
            MMA_BF16(acc[1][3], a[1][0],a[1][1],a[1][2],a[1][3], b[1][2],b[1][3]);
        }

        if (dt == 7) {
#pragma unroll
            for (int mt = 0; mt < 2; mt++)
#pragma unroll
                for (int nt = 0; nt < 4; nt++) {
                    int colb = wn*32 + nt*8 + tig*2;
                    float w0 = wsqs[colb], w1 = wsqs[colb+1];
                    int gc = kt * BN + colb;
                    float d00 = xsq_r[mt*2]   + w0 - 2.f*acc[mt][nt][0];
                    float d01 = xsq_r[mt*2]   + w1 - 2.f*acc[mt][nt][1];
                    float d10 = xsq_r[mt*2+1] + w0 - 2.f*acc[mt][nt][2];
                    float d11 = xsq_r[mt*2+1] + w1 - 2.f*acc[mt][nt][3];
                    topk_insert<3>(td[mt*2],   ti[mt*2],   d00, gc);
                    topk_insert<3>(td[mt*2],   ti[mt*2],   d01, gc+1);
                    topk_insert<3>(td[mt*2+1], ti[mt*2+1], d10, gc);
                    topk_insert<3>(td[mt*2+1], ti[mt*2+1], d11, gc+1);
                    acc[mt][nt][0] = 0.f; acc[mt][nt][1] = 0.f;
                    acc[mt][nt][2] = 0.f; acc[mt][nt][3] = 0.f;
                }
        }
    }
    __syncthreads();

    // cross-thread reduce: 16 owners/row x top-3 = 48 candidates -> top-8 (scratch over A)
    float* cd = (float*)dynsm;                          // [BM][48]
    int*   ci = (int*)(dynsm + BM*48*sizeof(float));    // [BM][48]
#pragma unroll
    for (int s = 0; s < 4; s++) {
        int rl = wm*32 + (s>>1)*16 + (s&1)*8 + gI;
        int cs = (wn*4 + tig)*3;
#pragma unroll
        for (int j = 0; j < 3; j++) {
            cd[rl*48 + cs + j] = td[s][j];
            ci[rl*48 + cs + j] = ti[s][j];
        }
    }
    __syncthreads();

    if (tid < BM) {
        float bd[8]; int bi[8];
#pragma unroll
        for (int s = 0; s < 8; s++) { bd[s] = INFINITY; bi[s] = 0x7fffffff; }
        for (int cc = 0; cc < 48; cc++)
            topk_insert<8>(bd, bi, cd[tid*48 + cc], ci[tid*48 + cc]);
        int r = row0 + tid;
#pragma unroll
        for (int s = 0; s < 8; s++) g_top8[r*8 + s] = bi[s];
    }
}

// ---------------- epilogue: exact refine (warp per candidate), weights, quantize, loss ----------------
__global__ __launch_bounds__(256)
void epilogue_kernel(const float* __restrict__ x, const float* __restrict__ emb,
                     float* __restrict__ out) {
    const int n = blockIdx.x;
    const int t = threadIdx.x;
    const int w = t >> 5, lane = t & 31;
    __shared__ int   cidx[8];
    __shared__ float dist8[8];
    __shared__ float ws[3];
    __shared__ int   sel[3];
    __shared__ float red[256];

    if (t < 8) cidx[t] = g_top8[n*8 + t];
    __syncthreads();

    {
        const float* xr = g_xn + (size_t)n * DDIM;
        const float* wr = g_wn + (size_t)cidx[w] * DDIM;
        float s = 0.f, c = 0.f;
#pragma unroll
        for (int i = 0; i < 16; i++)
            acc_prod(xr[lane + 32*i], wr[lane + 32*i], s, c);
#pragma unroll
        for (int o = 16; o; o >>= 1) {
            float os = __shfl_xor_sync(0xffffffffu, s, o);
            float oc = __shfl_xor_sync(0xffffffffu, c, o);
            float tt, e;
            twosum(s, os, tt, e);
            s = tt; c += oc + e;
        }
        if (lane == 0)
            dist8[w] = g_xsq[n] + g_wsq[cidx[w]] - 2.f * (s + c);
    }
    __syncthreads();

    if (t == 0) {
        float bd[3] = {INFINITY, INFINITY, INFINITY};
        int   bs[3] = {0, 0, 0};
        bool  hv[3] = {false, false, false};
        for (int c = 0; c < 8; c++) {
            float nd = dist8[c]; int ni = cidx[c];
            if (!hv[2] || nd < bd[2] || (nd == bd[2] && ni < cidx[bs[2]])) {
                if (!hv[1] || nd < bd[1] || (nd == bd[1] && ni < cidx[bs[1]])) {
                    bd[2] = bd[1]; bs[2] = bs[1]; hv[2] = hv[1];
                    if (!hv[0] || nd < bd[0] || (nd == bd[0] && ni < cidx[bs[0]])) {
                        bd[1] = bd[0]; bs[1] = bs[0]; hv[1] = hv[0];
                        bd[0] = nd;   bs[0] = c;     hv[0] = true;
                    } else { bd[1] = nd; bs[1] = c; hv[1] = true; }
                } else { bd[2] = nd; bs[2] = c; hv[2] = true; }
            }
        }
        float v0 = 1.f/bd[0], v1 = 1.f/bd[1], v2 = 1.f/bd[2];
        float ssum = (v0 + v1) + v2;
        ws[0] = v0/ssum; ws[1] = v1/ssum; ws[2] = v2/ssum;
        sel[0] = cidx[bs[0]]; sel[1] = cidx[bs[1]]; sel[2] = cidx[bs[2]];
        float* idx_out = out + (size_t)NROWS*DDIM + 1;
        idx_out[n*3+0] = (float)sel[0];
        idx_out[n*3+1] = (float)sel[1];
        idx_out[n*3+2] = (float)sel[2];
    }
    __syncthreads();

    const float w0 = ws[0], w1 = ws[1], w2 = ws[2];
    const float* e0 = emb + (size_t)sel[0]*DDIM;
    const float* e1 = emb + (size_t)sel[1]*DDIM;
    const float* e2 = emb + (size_t)sel[2]*DDIM;

    float local = 0.f;
#pragma unroll
    for (int d = t; d < DDIM; d += 256) {
        float q  = fmaf(w2, e2[d], fmaf(w1, e1[d], w0*e0[d]));
        float xv = x[(size_t)n*DDIM + d];
        float diff = q - xv;
        out[(size_t)n*DDIM + d] = xv + diff;
        local = fmaf(diff, diff, local);
    }
    red[t] = local;
    __syncthreads();
#pragma unroll
    for (int o = 128; o; o >>= 1) {
        if (t < o) red[t] += red[t+o];
        __syncthreads();
    }
    if (t == 0) g_rowsum[n] = red[0];
}

// ---------------- deterministic loss reduction ----------------
__global__ void loss_kernel(float* __restrict__ out) {
    __shared__ double red[256];
    int t = threadIdx.x;
    double s = 0.0;
    for (int i = t; i < NROWS; i += 256) s += (double)g_rowsum[i];
    red[t] = s;
    __syncthreads();
#pragma unroll
    for (int o = 128; o; o >>= 1) {
        if (t < o) red[t] += red[t+o];
        __syncthreads();
    }
    if (t == 0) {
        double mean = red[0] / (double)((size_t)NROWS*DDIM);
        out[(size_t)NROWS*DDIM] = (float)(1.25 * mean);
    }
}

// ---------------- launch ----------------
extern "C" void kernel_launch(void* const* d_in, const int* in_sizes, int n_in,
                              void* d_out, int out_size) {
    const float* x   = (const float*)d_in[0];
    const float* emb = (const float*)d_in[1];
    float* out = (float*)d_out;

    __nv_bfloat16 *p_xh, *p_wh;
    float *p_xn, *p_wn, *p_xsq, *p_wsq;
    cudaGetSymbolAddress((void**)&p_xh,  g_xh);
    cudaGetSymbolAddress((void**)&p_wh,  g_wh);
    cudaGetSymbolAddress((void**)&p_xn,  g_xn);
    cudaGetSymbolAddress((void**)&p_wn,  g_wn);
    cudaGetSymbolAddress((void**)&p_xsq, g_xsq);
    cudaGetSymbolAddress((void**)&p_wsq, g_wsq);

    cudaFuncSetAttribute(gemm_topk_kernel,
                         cudaFuncAttributeMaxDynamicSharedMemorySize, SMEM_BYTES);

    prep_kernel<<<KCB/8,   256>>>(emb, KCB,   p_wn, p_wh, p_wsq);
    prep_kernel<<<NROWS/8, 256>>>(x,   NROWS, p_xn, p_xh, p_xsq);
    gemm_topk_kernel<<<NROWS/BM, GEMM_THREADS, SMEM_BYTES>>>();
    epilogue_kernel<<<NROWS, 256>>>(x, emb, out);
    loss_kernel<<<1, 256>>>(out);
}

// round 17
// speedup vs baseline: 1.8139x; 1.0070x over previous
#include <cuda_runtime.h>
#include <cuda_bf16.h>
#include <math.h>
#include <stdint.h>

#define NROWS 32768
#define DDIM  512
#define KCB   8192
#define EPSF  1e-12f

#define BM 128
#define BN 128
#define BK 64
#define KSTA 520                   // A smem row stride (bf16): 1040B -> conflict-free LDSM
#define KSTB 72                    // B smem row stride (bf16): 144B  -> conflict-free LDSM
#define GEMM_THREADS 512
#define A_BYTES    (BM * KSTA * 2)            // 133120
#define BSTG_BYTES (BN * KSTB * 2)            // 18432
#define SMEM_BYTES (A_BYTES + 2 * BSTG_BYTES) // 169984
#define NSTEP ((KCB / BN) * (DDIM / BK))      // 64 * 8 = 512

// ---------------- device scratch ----------------
__device__ __align__(128) __nv_bfloat16 g_xh[(size_t)NROWS*DDIM];
__device__ __align__(128) __nv_bfloat16 g_wh[(size_t)KCB*DDIM];
__device__ __align__(128) float g_wn[(size_t)KCB*DDIM];
__device__ float g_xsq[NROWS];
__device__ float g_xnrm[NROWS];
__device__ float g_wsq[KCB];
__device__ int   g_top8[NROWS*8];
__device__ float g_rowsum[NROWS];

// ---------------- compensated arithmetic ----------------
__device__ __forceinline__ void twosum(float a, float b, float& s, float& e) {
    s = a + b;
    float bp = s - a;
    e = (a - (s - bp)) + (b - bp);
}
__device__ __forceinline__ void acc_prod(float x, float w, float& s, float& c) {
    float p = x * w;
    float pe = fmaf(x, w, -p);
    float t, e;
    twosum(s, p, t, e);
    s = t;
    c += e + pe;
}

// ---------------- prep: normalize -> bf16, exact xsq, optional fp32 vn / norm ----------------
__global__ void prep_kernel(const float* __restrict__ v, int rows,
                            float* __restrict__ vn,       // nullable
                            __nv_bfloat16* __restrict__ hi,
                            float* __restrict__ sq,
                            float* __restrict__ nrm_out) { // nullable
    int warp = (blockIdx.x * blockDim.x + threadIdx.x) >> 5;
    int lane = threadIdx.x & 31;
    if (warp >= rows) return;
    const float* row = v + (size_t)warp * DDIM;
    float vals[16];
    float s = 0.f;
#pragma unroll
    for (int i = 0; i < 16; i++) { vals[i] = row[lane + 32*i]; s = fmaf(vals[i], vals[i], s); }
#pragma unroll
    for (int o = 16; o; o >>= 1) s += __shfl_xor_sync(0xffffffffu, s, o);
    float nrm = fmaxf(sqrtf(s), EPSF);
    float s2 = 0.f, c2 = 0.f;
#pragma unroll
    for (int i = 0; i < 16; i++) {
        float xn = vals[i] / nrm;
        size_t off = (size_t)warp * DDIM + lane + 32*i;
        if (vn) vn[off] = xn;
        hi[off] = __float2bfloat16(xn);
        acc_prod(xn, xn, s2, c2);
    }
#pragma unroll
    for (int o = 16; o; o >>= 1) {
        float os = __shfl_xor_sync(0xffffffffu, s2, o);
        float oc = __shfl_xor_sync(0xffffffffu, c2, o);
        float t, e;
        twosum(s2, os, t, e);
        s2 = t; c2 += oc + e;
    }
    if (lane == 0) {
        sq[warp] = s2 + c2;
        if (nrm_out) nrm_out[warp] = nrm;
    }
}

// ---------------- top-S insert (tie: lower index wins) ----------------
template<int S>
__device__ __forceinline__ void topk_insert(float (&d)[S], int (&ix)[S], float nd, int ni) {
#pragma unroll
    for (int s = S - 1; s >= 0; s--) {
        bool better = (nd < d[s]) || (nd == d[s] && ni < ix[s]);
        if (!better) {
#pragma unroll
            for (int t = S - 1; t > s + 1; t--) { d[t] = d[t-1]; ix[t] = ix[t-1]; }
            if (s + 1 < S) { d[s+1] = nd; ix[s+1] = ni; }
            return;
        }
    }
#pragma unroll
    for (int t = S - 1; t > 0; t--) { d[t] = d[t-1]; ix[t] = ix[t-1]; }
    d[0] = nd; ix[0] = ni;
}

// ---------------- helpers ----------------
__device__ __forceinline__ uint32_t smem_u32(const void* p) {
    uint32_t a;
    asm("{ .reg .u64 t; cvta.to.shared.u64 t, %1; cvt.u32.u64 %0, t; }" : "=r"(a) : "l"(p));
    return a;
}
__device__ __forceinline__ void cp16(uint32_t sa, const void* g) {
    asm volatile("cp.async.cg.shared.global [%0], [%1], 16;" :: "r"(sa), "l"(g));
}
__device__ __forceinline__ void ldsm_x4(uint32_t (&r)[4], uint32_t addr) {
    asm volatile("ldmatrix.sync.aligned.m8n8.x4.shared.b16 {%0,%1,%2,%3}, [%4];"
                 : "=r"(r[0]), "=r"(r[1]), "=r"(r[2]), "=r"(r[3]) : "r"(addr));
}

#define MMA_BF16(C, A0, A1, A2, A3, B0, B1) \
    asm volatile("mma.sync.aligned.m16n8k16.row.col.f32.bf16.bf16.f32 " \
                 "{%0,%1,%2,%3},{%4,%5,%6,%7},{%8,%9},{%0,%1,%2,%3};" \
                 : "+f"(C[0]), "+f"(C[1]), "+f"(C[2]), "+f"(C[3]) \
                 : "r"(A0), "r"(A1), "r"(A2), "r"(A3), "r"(B0), "r"(B1))

// ---------------- A-resident bf16 GEMM + top-8 nomination (identical to R16) ----------------
__global__ __launch_bounds__(GEMM_THREADS, 1)
void gemm_topk_kernel() {
    extern __shared__ __align__(16) char dynsm[];
    __shared__ float wsqs[BN];

    const uint32_t sm0 = smem_u32(dynsm);
    const int tid  = threadIdx.x;
    const int warp = tid >> 5, lane = tid & 31;
    const int wm = warp >> 2, wn = warp & 3;   // 4x4 warp grid, warp tile 32x32
    const int gI = lane >> 2, tig = lane & 3;
    const int mat = lane >> 3, rowin = lane & 7;
    const int row0 = blockIdx.x * BM;

    // ---- A tile resident: 128 x 512 bf16, stride KSTA ----
#pragma unroll
    for (int i = 0; i < 16; i++) {
        int u = i * 512 + tid;            // 16B chunk id, 0..8191 (64 per row)
        int r = u >> 6, q = u & 63;
        cp16(sm0 + (uint32_t)(r * (KSTA*2) + q * 16),
             &g_xh[(size_t)(row0 + r) * DDIM + q * 8]);
    }
    asm volatile("cp.async.commit_group;");

    // ---- B chunk 0 prefetch (kt=0, dt=0) ----
    {
#pragma unroll
        for (int i = 0; i < 2; i++) {
            int u = i * 512 + tid;        // 0..1023
            int r = u >> 3, q = u & 7;
            cp16(sm0 + (uint32_t)(A_BYTES + r * (KSTB*2) + q * 16),
                 &g_wh[(size_t)r * DDIM + q * 8]);
        }
        asm volatile("cp.async.commit_group;");
    }

    // ldmatrix base offsets (k16 = 0)
    uint32_t offA[2], offB[2];
#pragma unroll
    for (int mt = 0; mt < 2; mt++)
        offA[mt] = (uint32_t)(((wm*32 + mt*16 + (mat&1)*8 + rowin) * KSTA
                               + (mat>>1)*8) * 2);
#pragma unroll
    for (int np = 0; np < 2; np++)
        offB[np] = (uint32_t)(A_BYTES + ((wn*32 + np*16 + (mat>>1)*8 + rowin) * KSTB
                               + (mat&1)*8) * 2);

    float xsq_r[4];
#pragma unroll
    for (int s = 0; s < 4; s++)
        xsq_r[s] = g_xsq[row0 + wm*32 + (s>>1)*16 + (s&1)*8 + gI];

    float td[4][3]; int ti[4][3];
#pragma unroll
    for (int s = 0; s < 4; s++) {
        td[s][0] = td[s][1] = td[s][2] = INFINITY;
        ti[s][0] = ti[s][1] = ti[s][2] = 0x7fffffff;
    }

    float acc[2][4][4];
#pragma unroll
    for (int mt = 0; mt < 2; mt++)
#pragma unroll
        for (int nt = 0; nt < 4; nt++)
#pragma unroll
            for (int j = 0; j < 4; j++) acc[mt][nt][j] = 0.f;

    for (int c = 0; c < NSTEP; c++) {
        const int kt = c >> 3, dt = c & 7;

        asm volatile("cp.async.wait_group 0;");
        __syncthreads();

        if (dt == 0 && tid < BN) wsqs[tid] = g_wsq[kt * BN + tid];

        if (c + 1 < NSTEP) {
            const int cn = c + 1;
            const int ktn = (cn >> 3) * BN, kofn = (cn & 7) * BK;
            const uint32_t stg = (uint32_t)(A_BYTES + (cn & 1) * BSTG_BYTES);
#pragma unroll
            for (int i = 0; i < 2; i++) {
                int u = i * 512 + tid;
                int r = u >> 3, q = u & 7;
                cp16(sm0 + stg + (uint32_t)(r * (KSTB*2) + q * 16),
                     &g_wh[(size_t)(ktn + r) * DDIM + kofn + q * 8]);
            }
            asm volatile("cp.async.commit_group;");
        }

        const uint32_t dtoffA = (uint32_t)(dt * BK * 2);           // bytes into A row
        const uint32_t bstg   = (uint32_t)((c & 1) * BSTG_BYTES);

#pragma unroll
        for (int k16 = 0; k16 < 4; k16++) {
            const uint32_t ka = dtoffA + (uint32_t)(k16 * 32);
            const uint32_t kb = bstg   + (uint32_t)(k16 * 32);
            uint32_t a[2][4], b[2][4];
            ldsm_x4(a[0], sm0 + offA[0] + ka);
            ldsm_x4(a[1], sm0 + offA[1] + ka);
            ldsm_x4(b[0], sm0 + offB[0] + kb);
            ldsm_x4(b[1], sm0 + offB[1] + kb);

            MMA_BF16(acc[0][0], a[0][0],a[0][1],a[0][2],a[0][3], b[0][0],b[0][1]);
            MMA_BF16(acc[0][1], a[0][0],a[0][1],a[0][2],a[0][3], b[0][2],b[0][3]);
            MMA_BF16(acc[0][2], a[0][0],a[0][1],a[0][2],a[0][3], b[1][0],b[1][1]);
            MMA_BF16(acc[0][3], a[0][0],a[0][1],a[0][2],a[0][3], b[1][2],b[1][3]);
            MMA_BF16(acc[1][0], a[1][0],a[1][1],a[1][2],a[1][3], b[0][0],b[0][1]);
            MMA_BF16(acc[1][1], a[1][0],a[1][1],a[1][2],a[1][3], b[0][2],b[0][3]);
            MMA_BF16(acc[1][2], a[1][0],a[1][1],a[1][2],a[1][3], b[1][0],b[1][1]);
            MMA_BF16(acc[1][3], a[1][0],a[1][1],a[1][2],a[1][3], b[1][2],b[1][3]);
        }

        if (dt == 7) {
#pragma unroll
            for (int mt = 0; mt < 2; mt++)
#pragma unroll
                for (int nt = 0; nt < 4; nt++) {
                    int colb = wn*32 + nt*8 + tig*2;
                    float w0 = wsqs[colb], w1 = wsqs[colb+1];
                    int gc = kt * BN + colb;
                    float d00 = xsq_r[mt*2]   + w0 - 2.f*acc[mt][nt][0];
                    float d01 = xsq_r[mt*2]   + w1 - 2.f*acc[mt][nt][1];
                    float d10 = xsq_r[mt*2+1] + w0 - 2.f*acc[mt][nt][2];
                    float d11 = xsq_r[mt*2+1] + w1 - 2.f*acc[mt][nt][3];
                    topk_insert<3>(td[mt*2],   ti[mt*2],   d00, gc);
                    topk_insert<3>(td[mt*2],   ti[mt*2],   d01, gc+1);
                    topk_insert<3>(td[mt*2+1], ti[mt*2+1], d10, gc);
                    topk_insert<3>(td[mt*2+1], ti[mt*2+1], d11, gc+1);
                    acc[mt][nt][0] = 0.f; acc[mt][nt][1] = 0.f;
                    acc[mt][nt][2] = 0.f; acc[mt][nt][3] = 0.f;
                }
        }
    }
    __syncthreads();

    // cross-thread reduce: 16 owners/row x top-3 = 48 candidates -> top-8 (scratch over A)
    float* cd = (float*)dynsm;                          // [BM][48]
    int*   ci = (int*)(dynsm + BM*48*sizeof(float));    // [BM][48]
#pragma unroll
    for (int s = 0; s < 4; s++) {
        int rl = wm*32 + (s>>1)*16 + (s&1)*8 + gI;
        int cs = (wn*4 + tig)*3;
#pragma unroll
        for (int j = 0; j < 3; j++) {
            cd[rl*48 + cs + j] = td[s][j];
            ci[rl*48 + cs + j] = ti[s][j];
        }
    }
    __syncthreads();

    if (tid < BM) {
        float bd[8]; int bi[8];
#pragma unroll
        for (int s = 0; s < 8; s++) { bd[s] = INFINITY; bi[s] = 0x7fffffff; }
        for (int cc = 0; cc < 48; cc++)
            topk_insert<8>(bd, bi, cd[tid*48 + cc], ci[tid*48 + cc]);
        int r = row0 + tid;
#pragma unroll
        for (int s = 0; s < 8; s++) g_top8[r*8 + s] = bi[s];
    }
}

// ---------------- epilogue: smem-staged x, on-the-fly xn (bit-identical division),
//                  exact refine (warp per candidate), weights, quantize, loss ----------------
__global__ __launch_bounds__(256)
void epilogue_kernel(const float* __restrict__ x, const float* __restrict__ emb,
                     float* __restrict__ out) {
    const int n = blockIdx.x;
    const int t = threadIdx.x;
    const int w = t >> 5, lane = t & 31;
    __shared__ float xs[DDIM];     // raw x row
    __shared__ float xns[DDIM];    // xn = x/nrm (same division as prep -> bit-identical)
    __shared__ int   cidx[8];
    __shared__ float dist8[8];
    __shared__ float ws[3];
    __shared__ int   sel[3];
    __shared__ float red[256];

    if (t < 8) cidx[t] = g_top8[n*8 + t];
    {
        const float nrm = g_xnrm[n];
#pragma unroll
        for (int d = t; d < DDIM; d += 256) {
            float xv = x[(size_t)n*DDIM + d];
            xs[d]  = xv;
            xns[d] = xv / nrm;
        }
    }
    __syncthreads();

    // warp w: compensated-exact dot(xn, wn[cidx[w]])
    {
        const float* wr = g_wn + (size_t)cidx[w] * DDIM;
        float s = 0.f, c = 0.f;
#pragma unroll
        for (int i = 0; i < 16; i++)
            acc_prod(xns[lane + 32*i], wr[lane + 32*i], s, c);
#pragma unroll
        for (int o = 16; o; o >>= 1) {
            float os = __shfl_xor_sync(0xffffffffu, s, o);
            float oc = __shfl_xor_sync(0xffffffffu, c, o);
            float tt, e;
            twosum(s, os, tt, e);
            s = tt; c += oc + e;
        }
        if (lane == 0)
            dist8[w] = g_xsq[n] + g_wsq[cidx[w]] - 2.f * (s + c);
    }
    __syncthreads();

    if (t == 0) {
        float bd[3] = {INFINITY, INFINITY, INFINITY};
        int   bs[3] = {0, 0, 0};
        bool  hv[3] = {false, false, false};
        for (int c = 0; c < 8; c++) {
            float nd = dist8[c]; int ni = cidx[c];
            if (!hv[2] || nd < bd[2] || (nd == bd[2] && ni < cidx[bs[2]])) {
                if (!hv[1] || nd < bd[1] || (nd == bd[1] && ni < cidx[bs[1]])) {
                    bd[2] = bd[1]; bs[2] = bs[1]; hv[2] = hv[1];
                    if (!hv[0] || nd < bd[0] || (nd == bd[0] && ni < cidx[bs[0]])) {
                        bd[1] = bd[0]; bs[1] = bs[0]; hv[1] = hv[0];
                        bd[0] = nd;   bs[0] = c;     hv[0] = true;
                    } else { bd[1] = nd; bs[1] = c; hv[1] = true; }
                } else { bd[2] = nd; bs[2] = c; hv[2] = true; }
            }
        }
        float v0 = 1.f/bd[0], v1 = 1.f/bd[1], v2 = 1.f/bd[2];
        float ssum = (v0 + v1) + v2;
        ws[0] = v0/ssum; ws[1] = v1/ssum; ws[2] = v2/ssum;
        sel[0] = cidx[bs[0]]; sel[1] = cidx[bs[1]]; sel[2] = cidx[bs[2]];
        float* idx_out = out + (size_t)NROWS*DDIM + 1;
        idx_out[n*3+0] = (float)sel[0];
        idx_out[n*3+1] = (float)sel[1];
        idx_out[n*3+2] = (float)sel[2];
    }
    __syncthreads();

    const float w0 = ws[0], w1 = ws[1], w2 = ws[2];
    const float* e0 = emb + (size_t)sel[0]*DDIM;
    const float* e1 = emb + (size_t)sel[1]*DDIM;
    const float* e2 = emb + (size_t)sel[2]*DDIM;

    float local = 0.f;
#pragma unroll
    for (int d = t; d < DDIM; d += 256) {
        float q  = fmaf(w2, e2[d], fmaf(w1, e1[d], w0*e0[d]));
        float xv = xs[d];
        float diff = q - xv;
        out[(size_t)n*DDIM + d] = xv + diff;
        local = fmaf(diff, diff, local);
    }
    red[t] = local;
    __syncthreads();
#pragma unroll
    for (int o = 128; o; o >>= 1) {
        if (t < o) red[t] += red[t+o];
        __syncthreads();
    }
    if (t == 0) g_rowsum[n] = red[0];
}

// ---------------- deterministic loss reduction ----------------
__global__ void loss_kernel(float* __restrict__ out) {
    __shared__ double red[256];
    int t = threadIdx.x;
    double s = 0.0;
    for (int i = t; i < NROWS; i += 256) s += (double)g_rowsum[i];
    red[t] = s;
    __syncthreads();
#pragma unroll
    for (int o = 128; o; o >>= 1) {
        if (t < o) red[t] += red[t+o];
        __syncthreads();
    }
    if (t == 0) {
        double mean = red[0] / (double)((size_t)NROWS*DDIM);
        out[(size_t)NROWS*DDIM] = (float)(1.25 * mean);
    }
}

// ---------------- launch ----------------
extern "C" void kernel_launch(void* const* d_in, const int* in_sizes, int n_in,
                              void* d_out, int out_size) {
    const float* x   = (const float*)d_in[0];
    const float* emb = (const float*)d_in[1];
    float* out = (float*)d_out;

    __nv_bfloat16 *p_xh, *p_wh;
    float *p_wn, *p_xsq, *p_xnrm, *p_wsq;
    cudaGetSymbolAddress((void**)&p_xh,   g_xh);
    cudaGetSymbolAddress((void**)&p_wh,   g_wh);
    cudaGetSymbolAddress((void**)&p_wn,   g_wn);
    cudaGetSymbolAddress((void**)&p_xsq,  g_xsq);
    cudaGetSymbolAddress((void**)&p_xnrm, g_xnrm);
    cudaGetSymbolAddress((void**)&p_wsq,  g_wsq);

    cudaFuncSetAttribute(gemm_topk_kernel,
                         cudaFuncAttributeMaxDynamicSharedMemorySize, SMEM_BYTES);

    // w: store fp32 wn (needed by refine); x: store norm only (xn recomputed bit-identically)
    prep_kernel<<<KCB/8,   256>>>(emb, KCB,   p_wn,          p_wh, p_wsq, (float*)nullptr);
    prep_kernel<<<NROWS/8, 256>>>(x,   NROWS, (float*)nullptr, p_xh, p_xsq, p_xnrm);
    gemm_topk_kernel<<<NROWS/BM, GEMM_THREADS, SMEM_BYTES>>>();
    epilogue_kernel<<<NROWS, 256>>>(x, emb, out);
    loss_kernel<<<1, 256>>>(out);
}